// round 5
// baseline (speedup 1.0000x reference)
#include <cuda_runtime.h>

#define Bn   64
#define Tn   512
#define DIn  512
#define Hn   1024
#define G4   4096
#define BT   (Bn * Tn)
#define NCTA 128
#define KT   128

// Scratch (device globals: sanctioned, no runtime allocation)
__device__ float g_xproj[(size_t)BT * G4];   // 512 MB: inputs @ W_ih^T + bias
__device__ float g_hbuf[2][Bn * Hn];         // h double buffer
__device__ unsigned g_cnt;                   // grid barrier count (self-restoring)
__device__ volatile unsigned g_gen;          // grid barrier generation (monotonic)

typedef unsigned long long u64;

__device__ __forceinline__ void ffma2(u64 &d, u64 a, u64 b) {
    asm volatile("fma.rn.f32x2 %0, %1, %2, %0;" : "+l"(d) : "l"(a), "l"(b));
}
__device__ __forceinline__ u64 splat2(float x) {
    u64 r; asm("mov.b64 %0, {%1, %1};" : "=l"(r) : "r"(__float_as_uint(x))); return r;
}
__device__ __forceinline__ float2 unpk(u64 v) {
    unsigned lo, hi;
    asm("mov.b64 {%0, %1}, %2;" : "=r"(lo), "=r"(hi) : "l"(v));
    float2 r; r.x = __uint_as_float(lo); r.y = __uint_as_float(hi); return r;
}

__device__ __forceinline__ void grid_sync() {
    __threadfence();          // make this CTA's global writes visible (all threads)
    __syncthreads();
    if (threadIdx.x == 0) {
        unsigned g = g_gen;   // volatile read (L2)
        if (atomicAdd(&g_cnt, 1u) == NCTA - 1) {
            g_cnt = 0;
            __threadfence();
            g_gen = g + 1;    // release
        } else {
            while (g_gen == g) { }
            __threadfence();  // acquire
        }
    }
    __syncthreads();
}

// ---------------------------------------------------------------------------
// Kernel 1: x_proj[b,t,:] = inputs[b,t,:] @ W_ih^T + (b_ih + b_hh)
// C (32768 x 4096) = A (32768 x 512) * W^T (W: 4096 x 512).
// BM=BN=64, BK=16, 256 threads, 4x4 per-thread tile, f32x2 packed FMA.
// ---------------------------------------------------------------------------
__global__ __launch_bounds__(256) void xproj_kernel(
    const float* __restrict__ A, const float* __restrict__ W,
    const float* __restrict__ b_ih, const float* __restrict__ b_hh)
{
    __shared__ float As[16][68];   // [k][m], pad 68 keeps 16B alignment
    __shared__ float Ws[16][68];   // [k][n]

    const int bm  = blockIdx.y * 64;
    const int bn  = blockIdx.x * 64;
    const int tid = threadIdx.x;
    const int tx  = tid & 15;       // n-tile
    const int ty  = tid >> 4;       // m-tile
    const int lr  = tid >> 2;       // loader row 0..63
    const int lc  = (tid & 3) << 2; // loader k-offset 0,4,8,12

    u64 acc[4][2];
#pragma unroll
    for (int i = 0; i < 4; i++) { acc[i][0] = 0ull; acc[i][1] = 0ull; }

    const float* Arow = A + (size_t)(bm + lr) * DIn + lc;
    const float* Wrow = W + (size_t)(bn + lr) * DIn + lc;

    for (int k0 = 0; k0 < DIn; k0 += 16) {
        float4 av = *(const float4*)(Arow + k0);
        float4 wv = *(const float4*)(Wrow + k0);
        __syncthreads();
        As[lc + 0][lr] = av.x; As[lc + 1][lr] = av.y;
        As[lc + 2][lr] = av.z; As[lc + 3][lr] = av.w;
        Ws[lc + 0][lr] = wv.x; Ws[lc + 1][lr] = wv.y;
        Ws[lc + 2][lr] = wv.z; Ws[lc + 3][lr] = wv.w;
        __syncthreads();
#pragma unroll
        for (int kk = 0; kk < 16; kk++) {
            float4 a = *(const float4*)&As[kk][ty << 2];
            ulonglong2 w = *(const ulonglong2*)&Ws[kk][tx << 2];
            u64 s;
            s = splat2(a.x); ffma2(acc[0][0], w.x, s); ffma2(acc[0][1], w.y, s);
            s = splat2(a.y); ffma2(acc[1][0], w.x, s); ffma2(acc[1][1], w.y, s);
            s = splat2(a.z); ffma2(acc[2][0], w.x, s); ffma2(acc[2][1], w.y, s);
            s = splat2(a.w); ffma2(acc[3][0], w.x, s); ffma2(acc[3][1], w.y, s);
        }
    }

    const int n0 = bn + (tx << 2);
    const float bb0 = b_ih[n0 + 0] + b_hh[n0 + 0];
    const float bb1 = b_ih[n0 + 1] + b_hh[n0 + 1];
    const float bb2 = b_ih[n0 + 2] + b_hh[n0 + 2];
    const float bb3 = b_ih[n0 + 3] + b_hh[n0 + 3];
#pragma unroll
    for (int i = 0; i < 4; i++) {
        float2 p0 = unpk(acc[i][0]);
        float2 p1 = unpk(acc[i][1]);
        float4 o = make_float4(p0.x + bb0, p0.y + bb1, p1.x + bb2, p1.y + bb3);
        *(float4*)&g_xproj[(size_t)(bm + (ty << 2) + i) * G4 + n0] = o;
    }
}

// ---------------------------------------------------------------------------
// Kernel 2: persistent LSTM recurrence. 128 CTAs x 256 threads, 1 CTA/SM.
// CTA c owns h-indices j in [8c, 8c+8): W_hh rows {g*1024 + j} (32 rows,
// 128 KB) pinned in smem for all 512 steps. c-state lives in smem. Per step:
//   gates = h_prev @ W_slice^T  (f32x2 FMA, h streamed through smem tiles)
//   + x_proj, activations, write hs/cs, publish h_new, grid barrier.
// ---------------------------------------------------------------------------
__global__ __launch_bounds__(256) void lstm_kernel(
    const float* __restrict__ W_hh, const int* __restrict__ length,
    float* __restrict__ out)
{
    extern __shared__ float sm[];
    float* W_s  = sm;                  // [1024][32] k-major, 32768 floats
    float* h_s  = W_s + 1024 * 32;     // [64][KT]
    float* gbuf = h_s + 64 * KT;       // [64][32]
    float* c_s  = gbuf + 64 * 32;      // [512]
    __shared__ int len_s[Bn];

    const int cta   = blockIdx.x;
    const int tid   = threadIdx.x;
    const int jbase = cta * 8;

    // Load W slice into smem, layout W_s[k*32 + r], r = gate*8 + jj.
    // Conflict-free STS (lane -> r), one-time cost.
    for (int i = tid; i < 32 * 256; i += 256) {
        int r    = i & 31;
        int k4   = (i >> 5) << 2;
        int grow = ((r >> 3) << 10) + jbase + (r & 7);
        float4 v = *(const float4*)&W_hh[(size_t)grow * Hn + k4];
        W_s[(k4 + 0) * 32 + r] = v.x; W_s[(k4 + 1) * 32 + r] = v.y;
        W_s[(k4 + 2) * 32 + r] = v.z; W_s[(k4 + 3) * 32 + r] = v.w;
    }
    for (int i = tid; i < 512; i += 256) c_s[i] = 0.f;
    for (int i = tid; i < 512; i += 256) g_hbuf[0][cta * 512 + i] = 0.f;
    if (tid < Bn) len_s[tid] = length[tid];
    grid_sync();   // h0 = 0 visible everywhere

    const int rq = tid & 7;    // r-quad: r = 4*rq .. 4*rq+3
    const int bp = tid >> 3;   // batch pair: b = 2*bp, 2*bp+1
    const int b0 = bp * 2, b1 = bp * 2 + 1;

    int p = 0;
    for (int t = 0; t < Tn; t++) {
        const float* hprev = g_hbuf[p];
        u64 a00 = 0ull, a01 = 0ull, a10 = 0ull, a11 = 0ull;

        for (int k0 = 0; k0 < Hn; k0 += KT) {
            __syncthreads();
            // Stage h tile (coalesced .cg loads; L1 is stale across steps)
#pragma unroll
            for (int i = 0; i < 8; i++) {
                int lin = i * 256 + tid;
                int bb  = lin >> 5;
                int kq  = (lin & 31) << 2;
                float4 v = __ldcg((const float4*)&hprev[bb * Hn + k0 + kq]);
                *(float4*)&h_s[bb * KT + kq] = v;
            }
            __syncthreads();
            const float* Wp  = W_s + k0 * 32 + (rq << 2);
            const float* hp0 = h_s + b0 * KT;
            const float* hp1 = h_s + b1 * KT;
#pragma unroll 8
            for (int kk = 0; kk < KT; kk++) {
                ulonglong2 w = *(const ulonglong2*)(Wp + kk * 32);
                u64 hh0 = splat2(hp0[kk]);
                u64 hh1 = splat2(hp1[kk]);
                ffma2(a00, w.x, hh0); ffma2(a01, w.y, hh0);
                ffma2(a10, w.x, hh1); ffma2(a11, w.y, hh1);
            }
        }

        // Scatter partial gates to smem for the (b, j) gather
        {
            ulonglong2 v0; v0.x = a00; v0.y = a01;
            *(ulonglong2*)&gbuf[b0 * 32 + (rq << 2)] = v0;
            ulonglong2 v1; v1.x = a10; v1.y = a11;
            *(ulonglong2*)&gbuf[b1 * 32 + (rq << 2)] = v1;
        }
        __syncthreads();

        float* hnext = g_hbuf[p ^ 1];
#pragma unroll
        for (int cc = 0; cc < 2; cc++) {
            int cell = cc * 256 + tid;      // 0..511 = b*8 + jj
            int b  = cell >> 3;
            int jj = cell & 7;
            size_t xb = ((size_t)(b * Tn + t)) * G4 + jbase + jj;
            float gi = gbuf[b * 32 +      jj] + g_xproj[xb];
            float gf = gbuf[b * 32 +  8 + jj] + g_xproj[xb + 1024];
            float gg = gbuf[b * 32 + 16 + jj] + g_xproj[xb + 2048];
            float go = gbuf[b * 32 + 24 + jj] + g_xproj[xb + 3072];
            float co = c_s[cell];
            float si = 1.f / (1.f + __expf(-gi));
            float sf = 1.f / (1.f + __expf(-gf));
            float so = 1.f / (1.f + __expf(-go));
            float tg = tanhf(gg);
            float cn = sf * co + si * tg;
            float hn = so * tanhf(cn);
            c_s[cell] = cn;

            size_t ob = ((size_t)(b * Tn + t)) * Hn + jbase + jj;
            out[ob] = hn;                                   // hs
            out[(size_t)BT * Hn + ob] = cn;                 // cs
            __stcg(&hnext[b * Hn + jbase + jj], hn);
            if (t == len_s[b] - 1) {                        // h_last / c_last
                out[(size_t)2 * BT * Hn + (size_t)b * Hn + jbase + jj] = hn;
                out[(size_t)2 * BT * Hn + (size_t)Bn * Hn + (size_t)b * Hn + jbase + jj] = cn;
            }
        }
        grid_sync();
        p ^= 1;
    }
}

// ---------------------------------------------------------------------------
extern "C" void kernel_launch(void* const* d_in, const int* in_sizes, int n_in,
                              void* d_out, int out_size)
{
    (void)in_sizes; (void)n_in; (void)out_size;
    const float* inputs = (const float*)d_in[0];
    const float* W_ih   = (const float*)d_in[1];
    const float* W_hh   = (const float*)d_in[2];
    const float* b_ih   = (const float*)d_in[3];
    const float* b_hh   = (const float*)d_in[4];
    const int*   length = (const int*)d_in[5];
    float* out = (float*)d_out;

    const int smem_bytes = (1024 * 32 + 64 * KT + 64 * 32 + 512) * 4;  // 174080
    cudaFuncSetAttribute(lstm_kernel,
                         cudaFuncAttributeMaxDynamicSharedMemorySize, smem_bytes);

    dim3 g1(G4 / 64, BT / 64);   // 64 x 512 CTAs
    xproj_kernel<<<g1, 256>>>(inputs, W_ih, b_ih, b_hh);
    lstm_kernel<<<NCTA, 256, smem_bytes>>>(W_hh, length, out);
}